// round 15
// baseline (speedup 1.0000x reference)
#include <cuda_runtime.h>

#define NEGV (-9e15f)

constexpr int N  = 512;
constexpr int F  = 64;
constexpr int BS = 8;
constexpr int RWARPS  = 2;            // rows per CTA (1 warp per row)
constexpr int THREADS = RWARPS * 32;  // 64
constexpr int OUT_OFF = BS * N * F;   // 262144
constexpr float L2E = 1.4426950408889634f;

__device__ __forceinline__ float ex2(float v) {
    float r;
    asm("ex2.approx.f32 %0, %1;" : "=f"(r) : "f"(v));
    return r;
}
// elu(v) = v>0 ? v : e^v - 1, single MUFU
__device__ __forceinline__ float elu(float v) {
    return (v > 0.f) ? v : (ex2(v * L2E) - 1.f);
}

__global__ __launch_bounds__(THREADS)
void gat_kernel(const float* __restrict__ x,    // [8,512,1]
                const int*   __restrict__ adj,  // [512,512]
                const float* __restrict__ ext,  // [8,512,8]
                const float* __restrict__ side, // [8,512,1]
                const float* __restrict__ W,    // [1,64]
                const float* __restrict__ a,    // [128,1]
                const float* __restrict__ WS,   // [1,64]
                const float* __restrict__ aS,   // [128,1]
                const float* __restrict__ WQ,   // [2,16]
                const float* __restrict__ WK,   // [2,16]
                const float* __restrict__ WV,   // [1,64]
                float* __restrict__ out)        // [2,8,512,64]
{
    // All 8 scalars pre-scaled by log2(e): every exp is a bare ex2.approx.
    __shared__ float  s_c[8];
    __shared__ float4 s_x4 [N / 4];            // x[b]    (2KB)
    __shared__ float4 s_sd4[N / 4];            // side[b] (2KB)
    __shared__ float2 s_rec[RWARPS][N];        // compacted (s|j, xj) records (8KB)

    const int tid  = threadIdx.x;
    const int lane = tid & 31;
    const int w    = tid >> 5;
    const int row  = blockIdx.x * RWARPS + w;  // b*512 + i (CTA: one batch)
    const int b    = row >> 9;
    const int i    = row & 511;

    // ---- prologue: warp w computes contractions w, w+2, w+4, w+6 ----
    #pragma unroll
    for (int k = w; k < 8; k += RWARPS) {
        float val;
        if (k < 4) {
            const float* Wp = (k < 2) ? W : WS;
            const float* ap = (k < 2) ? a : aS;
            const int off   = (k & 1) ? 64 : 0;
            val = Wp[lane] * ap[off + lane] + Wp[lane + 32] * ap[off + 32 + lane];
        } else {
            const int l16 = lane & 15;
            const float* q = WQ + (((k == 5) || (k == 7)) ? 16 : 0);
            const float* p = WK + ((k >= 6) ? 16 : 0);
            // 0.5 (dup half-lanes) * 0.25 (1/sqrt(16))
            val = q[l16] * p[l16] * 0.125f;
        }
        #pragma unroll
        for (int o = 16; o; o >>= 1) val += __shfl_xor_sync(0xffffffffu, val, o);
        if (lane == 0) s_c[k] = val * L2E;
    }

    // ---- CTA-cooperative staging: x[b], side[b] (2 iters each @64 thr) ----
    const float4* xb4 = (const float4*)(x    + (b << 9));
    const float4* sb4 = (const float4*)(side + (b << 9));
    #pragma unroll
    for (int idx = tid; idx < N / 4; idx += THREADS) {
        s_x4 [idx] = xb4[idx];
        s_sd4[idx] = sb4[idx];
    }
    __syncthreads();   // the ONLY cross-warp sync

    const float c1 = s_c[0], c2 = s_c[1], cs1 = s_c[2], cs2 = s_c[3];
    const float A0 = s_c[4], B0 = s_c[5], A1  = s_c[6], B1  = s_c[7];

    const float* sx = (const float*)s_x4;
    const float xi = sx[i];
    const float si = ((const float*)s_sd4)[i];
    const float t1 = xi * c1;        // log2 units
    const float t2 = si * cs1;
    const float xiA0 = xi * A0;
    const float xiA1 = xi * A1;

    const float4* extb4 = (const float4*)(ext + ((size_t)(b << 9) * 8));
    float ei[8];
    {
        float4 ea = __ldg(&extb4[2 * i]);
        float4 eb = __ldg(&extb4[2 * i + 1]);
        ei[0]=ea.x; ei[1]=ea.y; ei[2]=ea.z; ei[3]=ea.w;
        ei[4]=eb.x; ei[5]=eb.y; ei[6]=eb.z; ei[7]=eb.w;
    }
    const float mean_ei = (ei[0]+ei[1]+ei[2]+ei[3]+ei[4]+ei[5]+ei[6]+ei[7]) * 0.125f;

    // ---- Pass A: vectorized logits (4 j/lane), ballot compaction into
    //      float2 records {logit | j (low 9 mantissa bits), xj} ----
    float2* rl = s_rec[w];
    float lmax = NEGV;
    int   cnt  = 0;
    const int4* ar4 = (const int4*)(adj + (i << 9));
    #pragma unroll
    for (int blk = 0; blk < 4; blk++) {
        const int j0 = (blk << 7) + (lane << 2);
        int4   av = ar4[(blk << 5) + lane];
        float4 xv = s_x4 [(blk << 5) + lane];
        float4 sv = s_sd4[(blk << 5) + lane];
        #pragma unroll
        for (int k = 0; k < 4; k++) {
            float xj = (k==0)?xv.x:(k==1)?xv.y:(k==2)?xv.z:xv.w;
            float sj = (k==0)?sv.x:(k==1)?sv.y:(k==2)?sv.z:sv.w;
            int   ad = (k==0)?av.x:(k==1)?av.y:(k==2)?av.z:av.w;
            float e  = fmaf(c2,  xj, t1);  e  = fmaxf(e,  0.2f * e);  // leakyrelu
            float es = fmaf(cs2, sj, t2);  es = fmaxf(es, 0.2f * es);
            float s  = e + es;             // log2 units, > 0 when active
            bool act = (ad > 0) && (s > 0.f);
            unsigned mk = __ballot_sync(0xffffffffu, act);
            if (act) {
                int pos = cnt + __popc(mk & ((1u << lane) - 1u));
                unsigned qb = __float_as_uint(s) & ~0x1FFu;   // quantized logit
                rl[pos] = make_float2(__uint_as_float(qb | (unsigned)(j0 + k)), xj);
                lmax = fmaxf(lmax, __uint_as_float(qb));
            }
            cnt += __popc(mk);
        }
    }
    #pragma unroll
    for (int o = 16; o; o >>= 1)
        lmax = fmaxf(lmax, __shfl_xor_sync(0xffffffffu, lmax, o));
    float m = lmax;

    // Degenerate row (no active j): reference softmax is uniform over ALL 512 j
    // (p = exp(NEG-NEG) = 1). Encode logit bits 0, m=0 -> p = ex2(-0) = 1.
    if (cnt == 0) {
        m = 0.f;
        #pragma unroll
        for (int jj = 0; jj < N / 32; jj++) {
            int j = jj * 32 + lane;
            rl[j] = make_float2(__uint_as_float((unsigned)j), sx[j]);
        }
        cnt = N;
    }

    // ---- Pass B: sequential LDS.64 records; ext gather from global (L1) ----
    float den = 0.f, ynum = 0.f, znum = 0.f;
    for (int t = lane; t < cnt; t += 32) {
        float2 rc = rl[t];                         // sequential, conflict-free
        unsigned pk = __float_as_uint(rc.x);
        int   j  = pk & 0x1FFu;
        float p  = ex2(__uint_as_float(pk & ~0x1FFu) - m);
        float xj = rc.y;
        den  += p;
        ynum = fmaf(p, xj, ynum);
        float qk0 = fmaf(xj, B0, xiA0);            // log2-scaled
        float qk1 = fmaf(xj, B1, xiA1);
        float4 fa = __ldg(&extb4[2 * j]);          // L1 gather (16B x2)
        float4 fb = __ldg(&extb4[2 * j + 1]);
        float s8 = 0.f, wn = 0.f, df, pf;
        #define INNER(EIF, EJF) \
            df = fmaf(EIF, qk0, (EJF) * qk1); \
            pf = (df > 0.f) ? ex2(df) : 0.f; \
            s8 += pf;  wn = fmaf(pf, EIF, wn);
        INNER(ei[0], fa.x) INNER(ei[1], fa.y) INNER(ei[2], fa.z) INNER(ei[3], fa.w)
        INNER(ei[4], fb.x) INNER(ei[5], fb.y) INNER(ei[6], fb.z) INNER(ei[7], fb.w)
        #undef INNER
        // all-nonpositive inner row -> reference softmax uniform -> mean(ei)
        znum += p * ((s8 > 0.f) ? __fdividef(wn, s8) : mean_ei);
    }
    #pragma unroll
    for (int o = 16; o; o >>= 1) {
        den  += __shfl_xor_sync(0xffffffffu, den,  o);
        ynum += __shfl_xor_sync(0xffffffffu, ynum, o);
        znum += __shfl_xor_sync(0xffffffffu, znum, o);
    }
    const float y = __fdividef(ynum, den);
    const float z = __fdividef(znum, den);

    // ---- outputs: elu(y*W[f]), elu(z*WV[f]) ----
    size_t base = (size_t)row * F + lane;
    out[base]                = elu(y * W[lane]);
    out[base + 32]           = elu(y * W[lane + 32]);
    out[OUT_OFF + base]      = elu(z * WV[lane]);
    out[OUT_OFF + base + 32] = elu(z * WV[lane + 32]);
}

extern "C" void kernel_launch(void* const* d_in, const int* in_sizes, int n_in,
                              void* d_out, int out_size) {
    const float* input = (const float*)d_in[0];
    const int*   adj   = (const int*)  d_in[1];
    const float* ext   = (const float*)d_in[2];
    const float* side  = (const float*)d_in[3];
    const float* W     = (const float*)d_in[4];
    const float* a     = (const float*)d_in[5];
    const float* WS    = (const float*)d_in[6];
    const float* aS    = (const float*)d_in[7];
    const float* WQ    = (const float*)d_in[8];
    const float* WK    = (const float*)d_in[9];
    const float* WV    = (const float*)d_in[10];
    float* out = (float*)d_out;

    gat_kernel<<<(BS * N) / RWARPS, THREADS>>>(input, adj, ext, side,
                                               W, a, WS, aS, WQ, WK, WV, out);
}

// round 17
// speedup vs baseline: 1.1523x; 1.1523x over previous
#include <cuda_runtime.h>

#define NEGV (-9e15f)

constexpr int N  = 512;
constexpr int F  = 64;
constexpr int BS = 8;
constexpr int WARPS = 8;              // 1 warp per row, 8 rows per CTA (same b)
constexpr int THREADS = WARPS * 32;
constexpr int OUT_OFF = BS * N * F;   // 262144
constexpr float L2E = 1.4426950408889634f;

// dynamic smem layout (bytes):
//   [0,8192)        float4 s_ea[512]    ext[b] first halves  (16B stride)
//   [8192,16384)    float4 s_eb[512]    ext[b] second halves (16B stride)
//   [16384,20480)   float2 s_xsd[512]   interleaved (x_j, side_j)
//   [20480,53248)   float2 s_rec[8][512] compacted (s|j, xj) records
//   [53248,53280)   float  s_c[8]       scalar contractions
constexpr int SMEM_BYTES = 53280;

__device__ __forceinline__ float ex2(float v) {
    float r;
    asm("ex2.approx.f32 %0, %1;" : "=f"(r) : "f"(v));
    return r;
}
// elu(v) = v>0 ? v : e^v - 1, single MUFU
__device__ __forceinline__ float elu(float v) {
    return (v > 0.f) ? v : (ex2(v * L2E) - 1.f);
}
// packed f32x2 fma: (a.x*b.x+c.x, a.y*b.y+c.y) in one FFMA2
__device__ __forceinline__ float2 fma2(float2 a, float2 b, float2 c) {
    float2 r;
    asm("{\n\t"
        ".reg .b64 ra, rb, rc, rd;\n\t"
        "mov.b64 ra, {%2, %3};\n\t"
        "mov.b64 rb, {%4, %5};\n\t"
        "mov.b64 rc, {%6, %7};\n\t"
        "fma.rn.f32x2 rd, ra, rb, rc;\n\t"
        "mov.b64 {%0, %1}, rd;\n\t"
        "}" : "=f"(r.x), "=f"(r.y)
            : "f"(a.x), "f"(a.y), "f"(b.x), "f"(b.y), "f"(c.x), "f"(c.y));
    return r;
}

__global__ __launch_bounds__(THREADS)
void gat_kernel(const float* __restrict__ x,    // [8,512,1]
                const int*   __restrict__ adj,  // [512,512]
                const float* __restrict__ ext,  // [8,512,8]
                const float* __restrict__ side, // [8,512,1]
                const float* __restrict__ W,    // [1,64]
                const float* __restrict__ a,    // [128,1]
                const float* __restrict__ WS,   // [1,64]
                const float* __restrict__ aS,   // [128,1]
                const float* __restrict__ WQ,   // [2,16]
                const float* __restrict__ WK,   // [2,16]
                const float* __restrict__ WV,   // [1,64]
                float* __restrict__ out)        // [2,8,512,64]
{
    extern __shared__ char smem[];
    float4* s_ea  = (float4*)(smem);
    float4* s_eb  = (float4*)(smem + 8192);
    float2* s_xsd = (float2*)(smem + 16384);
    float2* s_rec = (float2*)(smem + 20480);
    float*  s_c   = (float*) (smem + 53248);

    const int tid  = threadIdx.x;
    const int lane = tid & 31;
    const int w    = tid >> 5;
    const int row  = blockIdx.x * WARPS + w;    // b*512 + i (CTA: one batch)
    const int b    = row >> 9;
    const int i    = row & 511;

    // ---- prologue: warp w computes scalar contraction w (scaled by L2E) ----
    {
        float val;
        if (w < 4) {
            const float* Wp = (w < 2) ? W : WS;
            const float* ap = (w < 2) ? a : aS;
            const int off   = (w & 1) ? 64 : 0;
            val = Wp[lane] * ap[off + lane] + Wp[lane + 32] * ap[off + 32 + lane];
        } else {
            const int l16 = lane & 15;
            const float* q = WQ + (((w == 5) || (w == 7)) ? 16 : 0);
            const float* k = WK + ((w >= 6) ? 16 : 0);
            // 0.5 (dup half-lanes) * 0.25 (1/sqrt(16))
            val = q[l16] * k[l16] * 0.125f;
        }
        #pragma unroll
        for (int o = 16; o; o >>= 1) val += __shfl_xor_sync(0xffffffffu, val, o);
        if (lane == 0) s_c[w] = val * L2E;
    }

    // ---- CTA-cooperative staging: interleaved (x,side), split ext halves ----
    const float4* xb4 = (const float4*)(x    + (b << 9));
    const float4* sb4 = (const float4*)(side + (b << 9));
    const float4* eb4 = (const float4*)(ext  + ((size_t)(b << 9) * 8));
    if (tid < N / 4) {
        float4 xv = xb4[tid], sv = sb4[tid];
        float4* o4 = (float4*)s_xsd;
        o4[2 * tid]     = make_float4(xv.x, sv.x, xv.y, sv.y);
        o4[2 * tid + 1] = make_float4(xv.z, sv.z, xv.w, sv.w);
    }
    #pragma unroll
    for (int idx = tid; idx < N * 2; idx += THREADS) {
        float4 v = eb4[idx];
        ((idx & 1) ? s_eb : s_ea)[idx >> 1] = v;
    }
    __syncthreads();   // the ONLY cross-warp sync

    const float c1 = s_c[0], c2 = s_c[1], cs1 = s_c[2], cs2 = s_c[3];
    const float A0 = s_c[4], B0 = s_c[5], A1  = s_c[6], B1  = s_c[7];

    const float2 xsi = s_xsd[i];
    const float xi = xsi.x;
    const float2 ccs = make_float2(c2, cs2);
    const float2 tts = make_float2(xi * c1, xsi.y * cs1);   // (t1, t2), log2 units
    const float xiA0 = xi * A0;
    const float xiA1 = xi * A1;

    float ei[8];
    {
        float4 ea = s_ea[i], eb = s_eb[i];
        ei[0]=ea.x; ei[1]=ea.y; ei[2]=ea.z; ei[3]=ea.w;
        ei[4]=eb.x; ei[5]=eb.y; ei[6]=eb.z; ei[7]=eb.w;
    }
    const float mean_ei = (ei[0]+ei[1]+ei[2]+ei[3]+ei[4]+ei[5]+ei[6]+ei[7]) * 0.125f;

    // ---- Pass A: packed logits (lrelu(a)+lrelu(b) = 0.6(a+b)+0.4(|a|+|b|)),
    //      ballot compaction into float2 records {logit|j, xj} ----
    float2* rl = s_rec + (w << 9);
    unsigned lmaxb = 0u;          // positive-float bits: integer max == float max
    int   cnt  = 0;
    const int4*   ar4 = (const int4*)(adj + (i << 9));
    const float4* xs4 = (const float4*)s_xsd;
    #pragma unroll
    for (int blk = 0; blk < 4; blk++) {
        const int j0 = (blk << 7) + (lane << 2);
        int4   av  = ar4[(blk << 5) + lane];
        float4 pa  = xs4[(blk << 6) + 2 * lane];      // (x0,s0,x1,s1)
        float4 pb  = xs4[(blk << 6) + 2 * lane + 1];  // (x2,s2,x3,s3)
        #pragma unroll
        for (int k = 0; k < 4; k++) {
            float2 pr = (k==0) ? make_float2(pa.x, pa.y)
                      : (k==1) ? make_float2(pa.z, pa.w)
                      : (k==2) ? make_float2(pb.x, pb.y)
                               : make_float2(pb.z, pb.w);
            int ad = (k==0)?av.x:(k==1)?av.y:(k==2)?av.z:av.w;
            float2 ab2 = fma2(pr, ccs, tts);          // a = c2*x+t1, b = cs2*sd+t2
            float abp  = ab2.x + ab2.y;
            float habs = fabsf(ab2.x) + fabsf(ab2.y);
            float s    = fmaf(0.6f, abp, 0.4f * habs); // = lrelu(a)+lrelu(b)
            bool act = (ad > 0) && (s > 0.f);
            unsigned mk = __ballot_sync(0xffffffffu, act);
            if (act) {
                int pos = cnt + __popc(mk & ((1u << lane) - 1u));
                unsigned qb = __float_as_uint(s) & ~0x1FFu;   // quantized logit
                rl[pos] = make_float2(__uint_as_float(qb | (unsigned)(j0 + k)), pr.x);
                lmaxb = max(lmaxb, qb);
            }
            cnt += __popc(mk);
        }
    }
    float m = __uint_as_float(__reduce_max_sync(0xffffffffu, lmaxb));

    // Degenerate row (no active j): reference softmax is uniform over ALL 512 j
    // (p = exp(NEG-NEG) = 1). Encode logit bits ~0, m=0 -> p = ex2(~0) = 1.
    if (cnt == 0) {
        m = 0.f;
        #pragma unroll
        for (int jj = 0; jj < N / 32; jj++) {
            int j = jj * 32 + lane;
            rl[j] = make_float2(__uint_as_float((unsigned)j), s_xsd[j].x);
        }
        cnt = N;
    }

    // ---- Pass B: sequential LDS.64 records; split-array ext gathers ----
    float den = 0.f, ynum = 0.f, znum = 0.f;
    for (int t = lane; t < cnt; t += 32) {
        float2 rc = rl[t];                         // sequential, conflict-free
        unsigned pk = __float_as_uint(rc.x);
        int   j  = pk & 0x1FFu;
        float p  = ex2(__uint_as_float(pk & ~0x1FFu) - m);
        float xj = rc.y;
        den  += p;
        ynum = fmaf(p, xj, ynum);
        float qk0 = fmaf(xj, B0, xiA0);            // log2-scaled
        float qk1 = fmaf(xj, B1, xiA1);
        float4 fa = s_ea[j];                       // 16B-stride gathers:
        float4 fb = s_eb[j];                       // fewer bank-group collisions
        float s8 = 0.f, wn = 0.f, df, pf;
        #define INNER(EIF, EJF) \
            df = fmaf(EIF, qk0, (EJF) * qk1); \
            pf = (df > 0.f) ? ex2(df) : 0.f; \
            s8 += pf;  wn = fmaf(pf, EIF, wn);
        INNER(ei[0], fa.x) INNER(ei[1], fa.y) INNER(ei[2], fa.z) INNER(ei[3], fa.w)
        INNER(ei[4], fb.x) INNER(ei[5], fb.y) INNER(ei[6], fb.z) INNER(ei[7], fb.w)
        #undef INNER
        // all-nonpositive inner row -> reference softmax uniform -> mean(ei)
        znum += p * ((s8 > 0.f) ? __fdividef(wn, s8) : mean_ei);
    }
    #pragma unroll
    for (int o = 16; o; o >>= 1) {
        den  += __shfl_xor_sync(0xffffffffu, den,  o);
        ynum += __shfl_xor_sync(0xffffffffu, ynum, o);
        znum += __shfl_xor_sync(0xffffffffu, znum, o);
    }
    const float y = __fdividef(ynum, den);
    const float z = __fdividef(znum, den);

    // ---- outputs: elu(y*W[f]), elu(z*WV[f]) ----
    size_t base = (size_t)row * F + lane;
    out[base]                = elu(y * W[lane]);
    out[base + 32]           = elu(y * W[lane + 32]);
    out[OUT_OFF + base]      = elu(z * WV[lane]);
    out[OUT_OFF + base + 32] = elu(z * WV[lane + 32]);
}

extern "C" void kernel_launch(void* const* d_in, const int* in_sizes, int n_in,
                              void* d_out, int out_size) {
    const float* input = (const float*)d_in[0];
    const int*   adj   = (const int*)  d_in[1];
    const float* ext   = (const float*)d_in[2];
    const float* side  = (const float*)d_in[3];
    const float* W     = (const float*)d_in[4];
    const float* a     = (const float*)d_in[5];
    const float* WS    = (const float*)d_in[6];
    const float* aS    = (const float*)d_in[7];
    const float* WQ    = (const float*)d_in[8];
    const float* WK    = (const float*)d_in[9];
    const float* WV    = (const float*)d_in[10];
    float* out = (float*)d_out;

    // idempotent, host-side, capture-safe (not a stream op, not an allocation)
    cudaFuncSetAttribute(gat_kernel,
                         cudaFuncAttributeMaxDynamicSharedMemorySize, SMEM_BYTES);

    gat_kernel<<<(BS * N) / WARPS, THREADS, SMEM_BYTES>>>(
        input, adj, ext, side, W, a, WS, aS, WQ, WK, WV, out);
}